// round 11
// baseline (speedup 1.0000x reference)
#include <cuda_runtime.h>
#include <cstdint>

// ---------------------------------------------------------------------------
// TreeCnnLayer: y[b,l,o] = relu( sum_{k=0..3} sum_i x[b, idx[l,k], i] * mask[k,i,o] + bias[127] )
// Gathered GEMM: M=131072, K=512, N=128.  mma.sync tf32 (plain sm_100 target).
// R11 (= R10 resubmit after infra failure): 128-thr CTAs @ (128,3), reg cap 170,
//      explicit ks+1 fragment double-buffering (A LDS + B LDG prefetch while
//      MMAs drain). CTA tile 64x128, warp tile 32x64, 12 warps/SM.
// ---------------------------------------------------------------------------

#define BATCH   16
#define NROWS   8192
#define TILE_M  64
#define NTILES  (NROWS / TILE_M)    // 128
#define BK      32
#define NCHUNK  16                  // 512 / 32
#define ASTR    36                  // A smem row stride (floats)

#define A_STAGE_B  (TILE_M * 144)   // 9216 B
#define SIDX_B     1024
#define NSTAGE     3
#define SMEM_TOTAL (SIDX_B + NSTAGE * A_STAGE_B)   // 28672

// Fragment-native B image: for k-step s (0..63), col-block nf (0..15), lane
// (0..31): float2 = (bb0, bb1) = W^T values at (o = nf*8 + lane/4,
// i = s*8 + lane%4 + {0,4}).  Warp load of one (s,nf) = 256 contiguous bytes.
__device__ float g_Bfrag[64 * 16 * 32 * 2];

__device__ __forceinline__ uint32_t smem_u32(const void* p) {
    uint32_t a;
    asm("{ .reg .u64 t; cvta.to.shared.u64 t, %1; cvt.u32.u64 %0, t; }" : "=r"(a) : "l"(p));
    return a;
}
__device__ __forceinline__ uint32_t f2tf32(float f) {
    uint32_t u;
    asm("cvt.rna.tf32.f32 %0, %1;" : "=r"(u) : "f"(f));
    return u;
}
__device__ __forceinline__ void cp_async16_cg(uint32_t dst, const void* src) {
    asm volatile("cp.async.cg.shared.global [%0], [%1], 16;" :: "r"(dst), "l"(src));
}
__device__ __forceinline__ void mma_tf32(float* d, const uint32_t* a, const uint32_t* b) {
    asm volatile(
        "mma.sync.aligned.m16n8k8.row.col.f32.tf32.tf32.f32 "
        "{%0,%1,%2,%3}, {%4,%5,%6,%7}, {%8,%9}, {%0,%1,%2,%3};"
        : "+f"(d[0]), "+f"(d[1]), "+f"(d[2]), "+f"(d[3])
        : "r"(a[0]), "r"(a[1]), "r"(a[2]), "r"(a[3]), "r"(b[0]), "r"(b[1]));
}

// ---------------- prep: build fragment-native tf32 B image ----------------
__global__ void prep_w_kernel(const float* __restrict__ mask) {
    int t = blockIdx.x * blockDim.x + threadIdx.x;   // 0..65535
    int j    = t & 1;
    int lane = (t >> 1) & 31;
    int nf   = (t >> 6) & 15;
    int s    = t >> 10;                              // k-step 0..63
    int qc = lane & 3, gr = lane >> 2;
    int o  = nf * 8 + gr;
    int ig = s * 8 + qc + 4 * j;                     // global k index 0..511
    int k  = ig >> 7, i = ig & 127;
    g_Bfrag[t] = __uint_as_float(f2tf32(mask[(k << 14) + (i << 7) + o]));
}

// ---------------- main kernel ----------------
__global__ void __launch_bounds__(128, 3)
tree_gemm(const float* __restrict__ x, const float* __restrict__ bias,
          const int* __restrict__ itab32, float* __restrict__ out)
{
    extern __shared__ char smem[];
    int* sIdx = (int*)smem;
    const uint32_t sbase = smem_u32(smem);

    const int tid  = threadIdx.x;
    const int lane = tid & 31;
    const int wid  = tid >> 5;          // 4 warps: 2M x 2N
    const int wm   = wid >> 1;          // 0..1
    const int wn   = wid & 1;           // 0..1
    const int gr   = lane >> 2;
    const int qc   = lane & 3;
    const int b    = blockIdx.y;
    const int V    = blockIdx.x * TILE_M;

    // index dtype autodetect (int64 LE: word[1]=hi(tab[0,0])=0; int32: tab[0,1]=8191)
    const int istride = (itab32[1] == 0) ? 2 : 1;
    const float bv = bias[127];

    #pragma unroll
    for (int j = tid; j < TILE_M * 4; j += 128) {
        int k = j >> 6, r = j & (TILE_M - 1);
        sIdx[j] = itab32[(size_t)(((V + r) << 2) + k) * istride];
    }
    __syncthreads();

    const char* xb = (const char*)(x + (size_t)b * NROWS * 128);

    // Per-warp B fragment pointer: (s, nf=wn*8, lane) -> float2
    const float2* Bf = (const float2*)g_Bfrag + (size_t)(wn * 8) * 32 + lane;

    // A stage byte offsets, rotated through registers.
    uint32_t aCur = SIDX_B;
    uint32_t aNxt = SIDX_B + A_STAGE_B;
    uint32_t aPre = SIDX_B + 2 * A_STAGE_B;

    auto load_chunk = [&](int c, uint32_t aOff) {
        const int k  = c >> 2;
        const int c0 = (c & 3) * BK;
        const uint32_t aB = sbase + aOff;
        // A: 64 rows x 32 floats, 16B segs; seg = r*8 + cs; 512 segs, 4/thread
        #pragma unroll
        for (int i = 0; i < 4; i++) {
            int seg = tid + i * 128;
            int r = seg >> 3, cs = seg & 7;
            int g = sIdx[(k << 6) + r];
            cp_async16_cg(aB + r * 144 + cs * 16,
                          xb + (((size_t)g << 7) + c0 + (cs << 2)) * 4);
        }
        asm volatile("cp.async.commit_group;");
    };

    float acc[2][8][4];
    #pragma unroll
    for (int mf = 0; mf < 2; mf++)
        #pragma unroll
        for (int nf = 0; nf < 8; nf++)
            #pragma unroll
            for (int q = 0; q < 4; q++) acc[mf][nf][q] = 0.0f;

    load_chunk(0, aCur);
    load_chunk(1, aNxt);

    // Double-buffered per-warp fragments (explicit prefetch distance 1 k-step).
    uint32_t aF[2][2][4];   // [buf][mf][frag]
    uint32_t bF[2][8][2];   // [buf][nf][frag]

    for (int c = 0; c < NCHUNK; c++) {
        if (c < NCHUNK - 1) asm volatile("cp.async.wait_group 1;");
        else                asm volatile("cp.async.wait_group 0;");
        __syncthreads();

        if (c + 2 < NCHUNK) load_chunk(c + 2, aPre);

        const float* A = (const float*)(smem + aCur);
        const float2* bfc = Bf + (size_t)(c << 2) * (16 * 32);

        // ---- fragment loader for k-step ks into buffer p ----
        auto load_frags = [&](int ks, int p) {
            const float2* bfp = bfc + (size_t)ks * (16 * 32);
            #pragma unroll
            for (int nf = 0; nf < 8; nf++) {
                float2 v = __ldg(bfp + nf * 32);
                bF[p][nf][0] = __float_as_uint(v.x);
                bF[p][nf][1] = __float_as_uint(v.y);
            }
            const int kc = ks << 3;
            #pragma unroll
            for (int mf = 0; mf < 2; mf++) {
                const float* ap = A + (wm * 32 + mf * 16 + gr) * ASTR + kc + qc;
                aF[p][mf][0] = f2tf32(ap[0]);
                aF[p][mf][1] = f2tf32(ap[8 * ASTR]);
                aF[p][mf][2] = f2tf32(ap[4]);
                aF[p][mf][3] = f2tf32(ap[8 * ASTR + 4]);
            }
        };

        load_frags(0, 0);
        #pragma unroll
        for (int ks = 0; ks < 4; ks++) {
            const int p = ks & 1;
            if (ks < 3) load_frags(ks + 1, p ^ 1);   // prefetch while MMAs drain
            #pragma unroll
            for (int mf = 0; mf < 2; mf++)
                #pragma unroll
                for (int nf = 0; nf < 8; nf++)
                    mma_tf32(acc[mf][nf], aF[p][mf], bF[p][nf]);
        }

        uint32_t t = aCur; aCur = aNxt; aNxt = aPre; aPre = t;
    }

    // ---- epilogue: +bias[127], relu, store ----
    float* ob = out + ((size_t)b * NROWS + V + wm * 32) * 128 + wn * 64;

    #pragma unroll
    for (int mf = 0; mf < 2; mf++) {
        #pragma unroll
        for (int nf = 0; nf < 8; nf++) {
            int row = mf * 16 + gr;
            int col = nf * 8 + 2 * qc;
            float2 v0, v1;
            v0.x = fmaxf(acc[mf][nf][0] + bv, 0.0f);
            v0.y = fmaxf(acc[mf][nf][1] + bv, 0.0f);
            v1.x = fmaxf(acc[mf][nf][2] + bv, 0.0f);
            v1.y = fmaxf(acc[mf][nf][3] + bv, 0.0f);
            *(float2*)(ob + (size_t)row * 128 + col)       = v0;
            *(float2*)(ob + (size_t)(row + 8) * 128 + col) = v1;
        }
    }
}

// ---------------- launch ----------------
extern "C" void kernel_launch(void* const* d_in, const int* in_sizes, int n_in,
                              void* d_out, int out_size)
{
    const float* x = nullptr;
    const float* mask = nullptr;
    const float* bias = nullptr;
    const int*   itab = nullptr;
    for (int i = 0; i < n_in; i++) {
        switch (in_sizes[i]) {
            case 16777216: x    = (const float*)d_in[i]; break;
            case 65536:    mask = (const float*)d_in[i]; break;
            case 128:      bias = (const float*)d_in[i]; break;
            case 32768:    itab = (const int*)d_in[i];   break;
            default: break;
        }
    }
    float* out = (float*)d_out;

    cudaFuncSetAttribute(tree_gemm,
                         cudaFuncAttributeMaxDynamicSharedMemorySize, SMEM_TOTAL);

    prep_w_kernel<<<256, 256>>>(mask);

    dim3 grid(NTILES, BATCH);
    tree_gemm<<<grid, 128, SMEM_TOTAL>>>(x, bias, itab, out);
}

// round 13
// speedup vs baseline: 1.3297x; 1.3297x over previous
#include <cuda_runtime.h>
#include <cstdint>

// ---------------------------------------------------------------------------
// TreeCnnLayer: y[b,l,o] = relu( sum_{k=0..3} sum_i x[b, idx[l,k], i] * mask[k,i,o] + bias[127] )
// Gathered GEMM: M=131072, K=512, N=128.  mma.sync tf32 (plain sm_100 target).
// R13 (= R12 resubmit after infra failure): A gather via cp.async.bulk (one
//      256B bulk copy per row per chunk, mbarrier complete_tx) to kill the
//      LDGSTS issue wall; B as paired fragment image (LDG.128 = two k-steps).
//      256 thr, 4Mx2N warps of 32x64, BK=64, double-buffered stages.
// ---------------------------------------------------------------------------

#define BATCH    16
#define NROWS    8192
#define TILE_M   128
#define NTILES   (NROWS / TILE_M)   // 64
#define NCHUNK   8                  // K=512 in chunks of 64 floats
#define APITCH_B 272                // A smem row pitch bytes (68 floats)
#define APITCH_F 68

#define A_STAGE_B  (TILE_M * APITCH_B)   // 34816
#define SIDX_B     2048
#define MBAR_OFF   2048                  // two 8B mbarriers at 2048 / 2056
#define STAGE0_OFF 2112
#define SMEM_TOTAL (STAGE0_OFF + 2 * A_STAGE_B)   // 71744

// Paired fragment-native B image: for k-step pair s2 (0..31), col-block nf
// (0..15), lane (0..31): float4 = (bb0,bb1 of step 2*s2, bb0,bb1 of 2*s2+1).
__device__ float g_Bp[32 * 16 * 32 * 4];

__device__ __forceinline__ uint32_t smem_u32(const void* p) {
    uint32_t a;
    asm("{ .reg .u64 t; cvta.to.shared.u64 t, %1; cvt.u32.u64 %0, t; }" : "=r"(a) : "l"(p));
    return a;
}
__device__ __forceinline__ uint32_t f2tf32(float f) {
    uint32_t u;
    asm("cvt.rna.tf32.f32 %0, %1;" : "=r"(u) : "f"(f));
    return u;
}
__device__ __forceinline__ void mma_tf32(float* d, const uint32_t* a, const uint32_t* b) {
    asm volatile(
        "mma.sync.aligned.m16n8k8.row.col.f32.tf32.tf32.f32 "
        "{%0,%1,%2,%3}, {%4,%5,%6,%7}, {%8,%9}, {%0,%1,%2,%3};"
        : "+f"(d[0]), "+f"(d[1]), "+f"(d[2]), "+f"(d[3])
        : "r"(a[0]), "r"(a[1]), "r"(a[2]), "r"(a[3]), "r"(b[0]), "r"(b[1]));
}
__device__ __forceinline__ void bulk_copy256(uint32_t dst, const void* src, uint32_t mbar) {
    asm volatile(
        "cp.async.bulk.shared::cluster.global.mbarrier::complete_tx::bytes "
        "[%0], [%1], 256, [%2];"
        :: "r"(dst), "l"(src), "r"(mbar) : "memory");
}
__device__ __forceinline__ void mbar_init(uint32_t mbar, uint32_t count) {
    asm volatile("mbarrier.init.shared.b64 [%0], %1;" :: "r"(mbar), "r"(count) : "memory");
}
__device__ __forceinline__ void mbar_expect_tx(uint32_t mbar, uint32_t bytes) {
    asm volatile("mbarrier.arrive.expect_tx.shared.b64 _, [%0], %1;"
                 :: "r"(mbar), "r"(bytes) : "memory");
}
__device__ __forceinline__ void mbar_wait(uint32_t mbar, uint32_t parity) {
    uint32_t done;
    asm volatile(
        "{\n\t.reg .pred p;\n\t"
        "mbarrier.try_wait.parity.acquire.cta.shared::cta.b64 p, [%1], %2;\n\t"
        "selp.b32 %0, 1, 0, p;\n\t}"
        : "=r"(done) : "r"(mbar), "r"(parity) : "memory");
    if (!done) {
        asm volatile(
            "{\n\t.reg .pred P1;\n\t"
            "WL_%=:\n\t"
            "mbarrier.try_wait.parity.acquire.cta.shared::cta.b64 P1, [%0], %1, 0x989680;\n\t"
            "@P1 bra.uni WD_%=;\n\t"
            "bra.uni WL_%=;\n\t"
            "WD_%=:\n\t}"
            :: "r"(mbar), "r"(parity) : "memory");
    }
}

// ---------------- prep: build paired fragment-native tf32 B image ----------
__global__ void prep_w_kernel(const float* __restrict__ mask) {
    int t = blockIdx.x * blockDim.x + threadIdx.x;   // 0..65535
    int j    = t & 3;
    int lane = (t >> 2) & 31;
    int nf   = (t >> 7) & 15;
    int s2   = t >> 11;                              // k-step pair 0..31
    int qc = lane & 3, gr = lane >> 2;
    int o  = nf * 8 + gr;
    int s  = 2 * s2 + (j >> 1);                      // k-step 0..63
    int ig = s * 8 + qc + 4 * (j & 1);               // global k 0..511
    int k  = ig >> 7, i = ig & 127;
    g_Bp[t] = __uint_as_float(f2tf32(mask[(k << 14) + (i << 7) + o]));
}

// ---------------- main kernel ----------------
__global__ void __launch_bounds__(256, 2)
tree_gemm(const float* __restrict__ x, const float* __restrict__ bias,
          const int* __restrict__ itab32, float* __restrict__ out)
{
    extern __shared__ char smem[];
    int* sIdx = (int*)smem;
    const uint32_t sbase = smem_u32(smem);
    const uint32_t mbarA[2] = { sbase + MBAR_OFF, sbase + MBAR_OFF + 8 };
    const uint32_t stOff[2] = { STAGE0_OFF, STAGE0_OFF + A_STAGE_B };

    const int tid  = threadIdx.x;
    const int lane = tid & 31;
    const int wid  = tid >> 5;          // 8 warps: 4M x 2N
    const int wm   = wid >> 1;          // 0..3
    const int wn   = wid & 1;           // 0..1
    const int gr   = lane >> 2;
    const int qc   = lane & 3;
    const int b    = blockIdx.y;
    const int V    = blockIdx.x * TILE_M;

    // index dtype autodetect (int64 LE: word[1]=hi(tab[0,0])=0; int32: tab[0,1]=8191)
    const int istride = (itab32[1] == 0) ? 2 : 1;
    const float bv = bias[127];

    #pragma unroll
    for (int j = tid; j < 512; j += 256) {
        int k = j >> 7, r = j & 127;
        sIdx[j] = itab32[(size_t)(((V + r) << 2) + k) * istride];
    }
    if (tid == 0) {
        mbar_init(mbarA[0], 1);
        mbar_init(mbarA[1], 1);
        mbar_expect_tx(mbarA[0], TILE_M * 256);
        mbar_expect_tx(mbarA[1], TILE_M * 256);
    }
    __syncthreads();

    const char* xb = (const char*)(x + (size_t)b * NROWS * 128);

    // Issue A chunk c into stage st: 128 bulk copies of 256 B (threads 0..127).
    auto issue_chunk = [&](int c, int st) {
        if (tid < TILE_M) {
            int g = sIdx[((c >> 1) << 7) + tid];
            const char* src = xb + (((size_t)g << 7) + (size_t)((c & 1) * 64)) * 4;
            bulk_copy256(sbase + stOff[st] + tid * APITCH_B, src, mbarA[st]);
        }
    };

    issue_chunk(0, 0);
    issue_chunk(1, 1);

    const float4* Bp = (const float4*)g_Bp;

    float acc[2][8][4];
    #pragma unroll
    for (int mf = 0; mf < 2; mf++)
        #pragma unroll
        for (int nf = 0; nf < 8; nf++)
            #pragma unroll
            for (int q = 0; q < 4; q++) acc[mf][nf][q] = 0.0f;

    int ph[2] = { 0, 0 };

    for (int c = 0; c < NCHUNK; c++) {
        const int st = c & 1;
        mbar_wait(mbarA[st], (uint32_t)ph[st]);
        ph[st] ^= 1;

        const float* A = (const float*)(smem + stOff[st]);

        #pragma unroll
        for (int sp = 0; sp < 4; sp++) {               // 4 k-step pairs / chunk
            const int gp = (c << 2) + sp;              // global pair 0..31
            const float4* bp = Bp + ((size_t)(gp * 16 + wn * 8) * 32) + lane;

            // A fragments for both steps of the pair
            uint32_t aF[2][2][4];
            #pragma unroll
            for (int e = 0; e < 2; e++) {
                const int kc = sp * 16 + e * 8;
                #pragma unroll
                for (int mf = 0; mf < 2; mf++) {
                    const float* ap = A + (wm * 32 + mf * 16 + gr) * APITCH_F + kc + qc;
                    aF[e][mf][0] = f2tf32(ap[0]);
                    aF[e][mf][1] = f2tf32(ap[8 * APITCH_F]);
                    aF[e][mf][2] = f2tf32(ap[4]);
                    aF[e][mf][3] = f2tf32(ap[8 * APITCH_F + 4]);
                }
            }
            // B + MMAs in nf-halves to bound register pressure
            #pragma unroll
            for (int h = 0; h < 2; h++) {
                float4 b4[4];
                #pragma unroll
                for (int q = 0; q < 4; q++) b4[q] = __ldg(bp + (h * 4 + q) * 32);
                #pragma unroll
                for (int e = 0; e < 2; e++) {
                    #pragma unroll
                    for (int q = 0; q < 4; q++) {
                        uint32_t bb[2];
                        bb[0] = __float_as_uint(e ? b4[q].z : b4[q].x);
                        bb[1] = __float_as_uint(e ? b4[q].w : b4[q].y);
                        #pragma unroll
                        for (int mf = 0; mf < 2; mf++)
                            mma_tf32(acc[mf][h * 4 + q], aF[e][mf], bb);
                    }
                }
            }
        }

        // Refill this stage with chunk c+2 (all reads of chunk c done for this
        // thread; barrier orders all threads' reads before any new copies).
        if (c + 2 < NCHUNK) {
            if (tid == 0) mbar_expect_tx(mbarA[st], TILE_M * 256);
        }
        __syncthreads();
        if (c + 2 < NCHUNK) issue_chunk(c + 2, st);
    }

    // ---- epilogue: +bias[127], relu, store ----
    float* ob = out + ((size_t)b * NROWS + V + wm * 32) * 128 + wn * 64;

    #pragma unroll
    for (int mf = 0; mf < 2; mf++) {
        #pragma unroll
        for (int nf = 0; nf < 8; nf++) {
            int row = mf * 16 + gr;
            int col = nf * 8 + 2 * qc;
            float2 v0, v1;
            v0.x = fmaxf(acc[mf][nf][0] + bv, 0.0f);
            v0.y = fmaxf(acc[mf][nf][1] + bv, 0.0f);
            v1.x = fmaxf(acc[mf][nf][2] + bv, 0.0f);
            v1.y = fmaxf(acc[mf][nf][3] + bv, 0.0f);
            *(float2*)(ob + (size_t)row * 128 + col)       = v0;
            *(float2*)(ob + (size_t)(row + 8) * 128 + col) = v1;
        }
    }
}

// ---------------- launch ----------------
extern "C" void kernel_launch(void* const* d_in, const int* in_sizes, int n_in,
                              void* d_out, int out_size)
{
    const float* x = nullptr;
    const float* mask = nullptr;
    const float* bias = nullptr;
    const int*   itab = nullptr;
    for (int i = 0; i < n_in; i++) {
        switch (in_sizes[i]) {
            case 16777216: x    = (const float*)d_in[i]; break;
            case 65536:    mask = (const float*)d_in[i]; break;
            case 128:      bias = (const float*)d_in[i]; break;
            case 32768:    itab = (const int*)d_in[i];   break;
            default: break;
        }
    }
    float* out = (float*)d_out;

    cudaFuncSetAttribute(tree_gemm,
                         cudaFuncAttributeMaxDynamicSharedMemorySize, SMEM_TOTAL);

    prep_w_kernel<<<256, 256>>>(mask);

    dim3 grid(NTILES, BATCH);
    tree_gemm<<<grid, 256, SMEM_TOTAL>>>(x, bias, itab, out);
}

// round 14
// speedup vs baseline: 1.3820x; 1.0393x over previous
#include <cuda_runtime.h>
#include <cstdint>

// ---------------------------------------------------------------------------
// TreeCnnLayer: y[b,l,o] = relu( sum_{k=0..3} sum_i x[b, idx[l,k], i] * mask[k,i,o] + bias[127] )
// Gathered GEMM: M=131072, K=512, N=128.  mma.sync tf32 (plain sm_100 target).
// R14: R13 (cp.async.bulk gather, paired B fragments) minus the per-chunk
//      __syncthreads. 3 A stages, each with its own full (tx) and read
//      (256-arrival) mbarrier; producers wait the read barrier of the stage
//      being recycled (completed one chunk ago -> ~free), consumers just
//      arrive. Warps may skew a full chunk -> cross-warp latency hiding.
// ---------------------------------------------------------------------------

#define BATCH    16
#define NROWS    8192
#define TILE_M   128
#define NTILES   (NROWS / TILE_M)   // 64
#define NCHUNK   8                  // K=512 in chunks of 64 floats
#define APITCH_B 272                // A smem row pitch bytes (68 floats)
#define APITCH_F 68

// Stage block: [full mbar 8B | read mbar 8B | pad to 64 | 128*272 data]
#define STAGE_STRIDE (64 + TILE_M * APITCH_B)    // 34880
#define SIDX_B     2048
#define STAGE_BASE 2048
#define SMEM_TOTAL (STAGE_BASE + 3 * STAGE_STRIDE)   // 106688

// Paired fragment-native B image: for k-step pair s2 (0..31), col-block nf
// (0..15), lane (0..31): float4 = (bb0,bb1 of step 2*s2, bb0,bb1 of 2*s2+1).
__device__ float g_Bp[32 * 16 * 32 * 4];

__device__ __forceinline__ uint32_t smem_u32(const void* p) {
    uint32_t a;
    asm("{ .reg .u64 t; cvta.to.shared.u64 t, %1; cvt.u32.u64 %0, t; }" : "=r"(a) : "l"(p));
    return a;
}
__device__ __forceinline__ uint32_t f2tf32(float f) {
    uint32_t u;
    asm("cvt.rna.tf32.f32 %0, %1;" : "=r"(u) : "f"(f));
    return u;
}
__device__ __forceinline__ void mma_tf32(float* d, const uint32_t* a, const uint32_t* b) {
    asm volatile(
        "mma.sync.aligned.m16n8k8.row.col.f32.tf32.tf32.f32 "
        "{%0,%1,%2,%3}, {%4,%5,%6,%7}, {%8,%9}, {%0,%1,%2,%3};"
        : "+f"(d[0]), "+f"(d[1]), "+f"(d[2]), "+f"(d[3])
        : "r"(a[0]), "r"(a[1]), "r"(a[2]), "r"(a[3]), "r"(b[0]), "r"(b[1]));
}
__device__ __forceinline__ void bulk_copy256(uint32_t dst, const void* src, uint32_t mbar) {
    asm volatile(
        "cp.async.bulk.shared::cluster.global.mbarrier::complete_tx::bytes "
        "[%0], [%1], 256, [%2];"
        :: "r"(dst), "l"(src), "r"(mbar) : "memory");
}
__device__ __forceinline__ void mbar_init(uint32_t mbar, uint32_t count) {
    asm volatile("mbarrier.init.shared.b64 [%0], %1;" :: "r"(mbar), "r"(count) : "memory");
}
__device__ __forceinline__ void mbar_expect_tx(uint32_t mbar, uint32_t bytes) {
    asm volatile("mbarrier.arrive.expect_tx.shared.b64 _, [%0], %1;"
                 :: "r"(mbar), "r"(bytes) : "memory");
}
__device__ __forceinline__ void mbar_arrive(uint32_t mbar) {
    asm volatile("mbarrier.arrive.shared.b64 _, [%0];" :: "r"(mbar) : "memory");
}
__device__ __forceinline__ void mbar_wait(uint32_t mbar, uint32_t parity) {
    uint32_t done;
    asm volatile(
        "{\n\t.reg .pred p;\n\t"
        "mbarrier.try_wait.parity.acquire.cta.shared::cta.b64 p, [%1], %2;\n\t"
        "selp.b32 %0, 1, 0, p;\n\t}"
        : "=r"(done) : "r"(mbar), "r"(parity) : "memory");
    if (!done) {
        asm volatile(
            "{\n\t.reg .pred P1;\n\t"
            "WL_%=:\n\t"
            "mbarrier.try_wait.parity.acquire.cta.shared::cta.b64 P1, [%0], %1, 0x989680;\n\t"
            "@P1 bra.uni WD_%=;\n\t"
            "bra.uni WL_%=;\n\t"
            "WD_%=:\n\t}"
            :: "r"(mbar), "r"(parity) : "memory");
    }
}

// ---------------- prep: build paired fragment-native tf32 B image ----------
__global__ void prep_w_kernel(const float* __restrict__ mask) {
    int t = blockIdx.x * blockDim.x + threadIdx.x;   // 0..65535
    int j    = t & 3;
    int lane = (t >> 2) & 31;
    int nf   = (t >> 7) & 15;
    int s2   = t >> 11;                              // k-step pair 0..31
    int qc = lane & 3, gr = lane >> 2;
    int o  = nf * 8 + gr;
    int s  = 2 * s2 + (j >> 1);                      // k-step 0..63
    int ig = s * 8 + qc + 4 * (j & 1);               // global k 0..511
    int k  = ig >> 7, i = ig & 127;
    g_Bp[t] = __uint_as_float(f2tf32(mask[(k << 14) + (i << 7) + o]));
}

// ---------------- main kernel ----------------
__global__ void __launch_bounds__(256, 2)
tree_gemm(const float* __restrict__ x, const float* __restrict__ bias,
          const int* __restrict__ itab32, float* __restrict__ out)
{
    extern __shared__ char smem[];
    int* sIdx = (int*)smem;
    const uint32_t sbase = smem_u32(smem);

    const int tid  = threadIdx.x;
    const int lane = tid & 31;
    const int wid  = tid >> 5;          // 8 warps: 4M x 2N
    const int wm   = wid >> 1;          // 0..3
    const int wn   = wid & 1;           // 0..1
    const int gr   = lane >> 2;
    const int qc   = lane & 3;
    const int b    = blockIdx.y;
    const int V    = blockIdx.x * TILE_M;

    // index dtype autodetect (int64 LE: word[1]=hi(tab[0,0])=0; int32: tab[0,1]=8191)
    const int istride = (itab32[1] == 0) ? 2 : 1;
    const float bv = bias[127];

    #pragma unroll
    for (int j = tid; j < 512; j += 256) {
        int k = j >> 7, r = j & 127;
        sIdx[j] = itab32[(size_t)(((V + r) << 2) + k) * istride];
    }
    if (tid == 0) {
        #pragma unroll
        for (int s = 0; s < 3; s++) {
            mbar_init(sbase + STAGE_BASE + s * STAGE_STRIDE, 1);        // full
            mbar_init(sbase + STAGE_BASE + s * STAGE_STRIDE + 8, 256);  // read
        }
        mbar_expect_tx(sbase + STAGE_BASE + 0 * STAGE_STRIDE, TILE_M * 256);
        mbar_expect_tx(sbase + STAGE_BASE + 1 * STAGE_STRIDE, TILE_M * 256);
    }
    __syncthreads();

    const char* xb = (const char*)(x + (size_t)b * NROWS * 128);

    // Issue A chunk c into stage at byte offset stOff (threads 0..127).
    auto issue_chunk = [&](int c, uint32_t stOff) {
        if (tid < TILE_M) {
            int g = sIdx[((c >> 1) << 7) + tid];
            const char* src = xb + (((size_t)g << 7) + (size_t)((c & 1) * 64)) * 4;
            bulk_copy256(sbase + stOff + 64 + tid * APITCH_B, src, sbase + stOff);
        }
    };

    issue_chunk(0, STAGE_BASE + 0 * STAGE_STRIDE);
    issue_chunk(1, STAGE_BASE + 1 * STAGE_STRIDE);

    const float4* Bp = (const float4*)g_Bp;

    float acc[2][8][4];
    #pragma unroll
    for (int mf = 0; mf < 2; mf++)
        #pragma unroll
        for (int nf = 0; nf < 8; nf++)
            #pragma unroll
            for (int q = 0; q < 4; q++) acc[mf][nf][q] = 0.0f;

    // Rotating stage offsets + phase bits (no modulo, no dynamic indexing).
    uint32_t stCur = STAGE_BASE;
    uint32_t stNxt = STAGE_BASE + STAGE_STRIDE;
    uint32_t stPre = STAGE_BASE + 2 * STAGE_STRIDE;
    int fpCur = 0, fpNxt = 0, fpPre = 0;   // full-barrier phases
    int rpCur = 0, rpNxt = 0, rpPre = 0;   // read-barrier phases

    for (int c = 0; c < NCHUNK; c++) {
        // ---- refill recycled stage with chunk c+2 (overlaps compute) ----
        if (c + 2 < NCHUNK) {
            if (c >= 1) {                       // stPre's first fill needs no wait
                mbar_wait(sbase + stPre + 8, (uint32_t)rpPre);  // readers of c-1 done
                rpPre ^= 1;
            }
            if (tid == 0) mbar_expect_tx(sbase + stPre, TILE_M * 256);
            issue_chunk(c + 2, stPre);
        }

        // ---- consume chunk c ----
        mbar_wait(sbase + stCur, (uint32_t)fpCur);
        fpCur ^= 1;

        const float* A = (const float*)(smem + stCur + 64);

        #pragma unroll
        for (int sp = 0; sp < 4; sp++) {               // 4 k-step pairs / chunk
            const int gp = (c << 2) + sp;              // global pair 0..31
            const float4* bp = Bp + ((size_t)(gp * 16 + wn * 8) * 32) + lane;

            uint32_t aF[2][2][4];
            #pragma unroll
            for (int e = 0; e < 2; e++) {
                const int kc = sp * 16 + e * 8;
                #pragma unroll
                for (int mf = 0; mf < 2; mf++) {
                    const float* ap = A + (wm * 32 + mf * 16 + gr) * APITCH_F + kc + qc;
                    aF[e][mf][0] = f2tf32(ap[0]);
                    aF[e][mf][1] = f2tf32(ap[8 * APITCH_F]);
                    aF[e][mf][2] = f2tf32(ap[4]);
                    aF[e][mf][3] = f2tf32(ap[8 * APITCH_F + 4]);
                }
            }
            #pragma unroll
            for (int h = 0; h < 2; h++) {
                float4 b4[4];
                #pragma unroll
                for (int q = 0; q < 4; q++) b4[q] = __ldg(bp + (h * 4 + q) * 32);
                #pragma unroll
                for (int e = 0; e < 2; e++) {
                    #pragma unroll
                    for (int q = 0; q < 4; q++) {
                        uint32_t bb[2];
                        bb[0] = __float_as_uint(e ? b4[q].z : b4[q].x);
                        bb[1] = __float_as_uint(e ? b4[q].w : b4[q].y);
                        #pragma unroll
                        for (int mf = 0; mf < 2; mf++)
                            mma_tf32(acc[mf][h * 4 + q], aF[e][mf], bb);
                    }
                }
            }
        }

        // Done reading stage stCur for this thread.
        mbar_arrive(sbase + stCur + 8);

        // rotate (cur, nxt, pre) <- (nxt, pre, cur), phases alongside
        uint32_t t = stCur; stCur = stNxt; stNxt = stPre; stPre = t;
        int tp = fpCur; fpCur = fpNxt; fpNxt = fpPre; fpPre = tp;
        tp = rpCur; rpCur = rpNxt; rpNxt = rpPre; rpPre = tp;
    }

    // ---- epilogue: +bias[127], relu, store ----
    float* ob = out + ((size_t)b * NROWS + V + wm * 32) * 128 + wn * 64;

    #pragma unroll
    for (int mf = 0; mf < 2; mf++) {
        #pragma unroll
        for (int nf = 0; nf < 8; nf++) {
            int row = mf * 16 + gr;
            int col = nf * 8 + 2 * qc;
            float2 v0, v1;
            v0.x = fmaxf(acc[mf][nf][0] + bv, 0.0f);
            v0.y = fmaxf(acc[mf][nf][1] + bv, 0.0f);
            v1.x = fmaxf(acc[mf][nf][2] + bv, 0.0f);
            v1.y = fmaxf(acc[mf][nf][3] + bv, 0.0f);
            *(float2*)(ob + (size_t)row * 128 + col)       = v0;
            *(float2*)(ob + (size_t)(row + 8) * 128 + col) = v1;
        }
    }
}

// ---------------- launch ----------------
extern "C" void kernel_launch(void* const* d_in, const int* in_sizes, int n_in,
                              void* d_out, int out_size)
{
    const float* x = nullptr;
    const float* mask = nullptr;
    const float* bias = nullptr;
    const int*   itab = nullptr;
    for (int i = 0; i < n_in; i++) {
        switch (in_sizes[i]) {
            case 16777216: x    = (const float*)d_in[i]; break;
            case 65536:    mask = (const float*)d_in[i]; break;
            case 128:      bias = (const float*)d_in[i]; break;
            case 32768:    itab = (const int*)d_in[i];   break;
            default: break;
        }
    }
    float* out = (float*)d_out;

    cudaFuncSetAttribute(tree_gemm,
                         cudaFuncAttributeMaxDynamicSharedMemorySize, SMEM_TOTAL);

    prep_w_kernel<<<256, 256>>>(mask);

    dim3 grid(NTILES, BATCH);
    tree_gemm<<<grid, 256, SMEM_TOTAL>>>(x, bias, itab, out);
}